// round 5
// baseline (speedup 1.0000x reference)
#include <cuda_runtime.h>
#include <cuda_bf16.h>
#include <cstdint>

// ---------------- problem constants ----------------
#define HH 128
#define WW 256
#define HW (HH*WW)          // 32768
#define CC 256
#define NSAMP (HW*9)        // 294912

// ---------------- static device scratch ----------------
__device__ __nv_bfloat16 g_XTh[(size_t)HW*CC];
__device__ __nv_bfloat16 g_XTl[(size_t)HW*CC];
__device__ int           g_idx[NSAMP];
__device__ __nv_bfloat16 g_Wh[4*CC*CC];   // q,k,v,o (q|k|v rows = fused B)
__device__ __nv_bfloat16 g_Wl[4*CC*CC];
__device__ float         g_bqkv[3*CC];
__device__ float         g_QKV[(size_t)HW*3*CC];   // [pixel][768] = Q|K|V
__device__ __nv_bfloat16 g_OUTh[(size_t)HW*CC];
__device__ __nv_bfloat16 g_OUTl[(size_t)HW*CC];

// ---------------- helpers ----------------
__device__ __forceinline__ uint32_t smem_u32(const void* p) {
    uint32_t a;
    asm("{ .reg .u64 t; cvta.to.shared.u64 t, %1; cvt.u32.u64 %0, t; }" : "=r"(a) : "l"(p));
    return a;
}
#define LDSM_X4(r, a) \
    asm volatile("ldmatrix.sync.aligned.m8n8.x4.shared.b16 {%0,%1,%2,%3}, [%4];" \
        : "=r"((r)[0]), "=r"((r)[1]), "=r"((r)[2]), "=r"((r)[3]) : "r"(a))

#define MMA16816(d, a, b) \
    asm volatile("mma.sync.aligned.m16n8k16.row.col.f32.bf16.bf16.f32 " \
        "{%0,%1,%2,%3}, {%4,%5,%6,%7}, {%8,%9}, {%0,%1,%2,%3};" \
        : "+f"((d)[0]), "+f"((d)[1]), "+f"((d)[2]), "+f"((d)[3]) \
        : "r"((a)[0]), "r"((a)[1]), "r"((a)[2]), "r"((a)[3]), "r"((b)[0]), "r"((b)[1]))

#define CP16(dst, src) \
    asm volatile("cp.async.cg.shared.global [%0], [%1], 16;" :: "r"(dst), "l"(src))
#define CP_COMMIT() asm volatile("cp.async.commit_group;")
#define CP_WAIT0()  asm volatile("cp.async.wait_group 0;")

// SMEM layout (bytes), per buffer: A_hi(256x80) A_lo B_hi(128x80) B_lo
#define LDS_ROW 80
#define A_PL    (256*LDS_ROW)        // 20480
#define B_PL    (128*LDS_ROW)        // 10240
#define BUF_SZ  (2*A_PL + 2*B_PL)    // 61440
#define B_OFF   (2*A_PL)             // 40960
#define SMEM_SZ (2*BUF_SZ)           // 122880

// ---------------- index computation ----------------
__global__ void idx_kernel(const float* __restrict__ grid, int* __restrict__ idx)
{
    int s = blockIdx.x * 256 + threadIdx.x;
    if (s >= NSAMP) return;
    int p  = s / 9;
    int t  = s - p * 9;
    int h  = p >> 8;
    int w  = p & 255;
    int kh = t / 3;
    int kw = t - kh * 3;
    const float* g = grid + ((size_t)(h * 3 + kh) * 768 + (w * 3 + kw)) * 2;
    float fx = rintf(((g[0] + 1.0f) * 0.5f) * 255.0f);
    float fy = rintf(((g[1] + 1.0f) * 0.5f) * 127.0f);
    int ix = (int)fminf(fmaxf(fx, 0.0f), 255.0f);
    int iy = (int)fminf(fmaxf(fy, 0.0f), 127.0f);
    idx[s] = iy * WW + ix;
}

// ---------------- transpose x[C][HW] -> XTh/XTl [HW][C] ----------------
__global__ void transpose_conv(const float* __restrict__ in,
                               __nv_bfloat16* __restrict__ oh, __nv_bfloat16* __restrict__ ol)
{
    __shared__ float tile[32][33];
    int c0 = blockIdx.x * 32;   // hw
    int r0 = blockIdx.y * 32;   // channel
    int tx = threadIdx.x, ty = threadIdx.y;
#pragma unroll
    for (int i = 0; i < 32; i += 8)
        tile[ty + i][tx] = in[(size_t)(r0 + ty + i) * HW + c0 + tx];
    __syncthreads();
#pragma unroll
    for (int i = 0; i < 32; i += 8) {
        float v = tile[tx][ty + i];
        __nv_bfloat16 h = __float2bfloat16(v);
        size_t o = (size_t)(c0 + ty + i) * CC + r0 + tx;
        oh[o] = h;
        ol[o] = __float2bfloat16(v - __bfloat162float(h));
    }
}

// ---------------- fused weight/bias prep: 4 matrices hi/lo + bias concat ----------------
__global__ void prep_weights(const float* __restrict__ wq, const float* __restrict__ wk,
                             const float* __restrict__ wv, const float* __restrict__ wo,
                             const float* __restrict__ bq, const float* __restrict__ bk,
                             const float* __restrict__ bv,
                             __nv_bfloat16* __restrict__ Wh, __nv_bfloat16* __restrict__ Wl,
                             float* __restrict__ bqkv)
{
    int i = blockIdx.x * 256 + threadIdx.x;
    if (i < 4 * CC * CC) {
        int m = i >> 16;                 // which matrix
        int j = i & 0xFFFF;
        const float* src = (m == 0) ? wq : (m == 1) ? wk : (m == 2) ? wv : wo;
        float v = src[j];
        __nv_bfloat16 hi = __float2bfloat16(v);
        Wh[i] = hi;
        Wl[i] = __float2bfloat16(v - __bfloat162float(hi));
    } else {
        int j = i - 4 * CC * CC;
        if (j < 768)
            bqkv[j] = (j < 256) ? bq[j] : ((j < 512) ? bk[j - 256] : bv[j - 512]);
    }
}

// ---------------- HMMA bf16-split GEMM, CTA tile 256x128, warp tile 64x64 ----------------
// C[M][N] = A[M][256] * B[N][256]^T + bias.  A,B bf16 hi/lo, K-contiguous rows (256 each).
// ROWBIAS: bias per m, else per n.
template<bool ROWBIAS>
__global__ __launch_bounds__(256, 1)
void hmma_gemm(const __nv_bfloat16* __restrict__ Ah, const __nv_bfloat16* __restrict__ Al,
               const __nv_bfloat16* __restrict__ Bh, const __nv_bfloat16* __restrict__ Bl,
               const float* __restrict__ bias, float* __restrict__ C, int ldc)
{
    extern __shared__ __align__(16) char sm[];
    uint32_t smb = smem_u32(sm);
    int tid = threadIdx.x;
    int wid = tid >> 5, lane = tid & 31;
    int wm = wid >> 1, wn = wid & 1;
    int m0 = blockIdx.y * 256, n0 = blockIdx.x * 128;

    // cp.async source pointers (per ks slice of 32 k = 64B per plane per row)
    const char* srcAh = (const char*)(Ah + (size_t)(m0 + tid) * 256);
    const char* srcAl = (const char*)(Al + (size_t)(m0 + tid) * 256);
    int brow = tid >> 1, bch = (tid & 1) * 2;
    const char* srcBh = (const char*)(Bh + (size_t)(n0 + brow) * 256);
    const char* srcBl = (const char*)(Bl + (size_t)(n0 + brow) * 256);

    uint32_t dA  = smb + tid * LDS_ROW;
    uint32_t dB  = smb + B_OFF + brow * LDS_ROW + bch * 16;

    // ldmatrix fragment addresses (buffer 0, hi planes)
    uint32_t aAddr[4], bAddr[4];
#pragma unroll
    for (int mt = 0; mt < 4; mt++)
        aAddr[mt] = smb + (wm * 64 + mt * 16 + (lane & 15)) * LDS_ROW + ((lane >> 4) * 16);
#pragma unroll
    for (int bt = 0; bt < 4; bt++)
        bAddr[bt] = smb + B_OFF + (wn * 64 + bt * 16 + ((lane >> 4) & 1) * 8 + (lane & 7)) * LDS_ROW
                  + (((lane >> 3) & 1) * 16);

    float acc[4][8][4];
#pragma unroll
    for (int i = 0; i < 4; i++)
#pragma unroll
        for (int j = 0; j < 8; j++)
#pragma unroll
            for (int k = 0; k < 4; k++) acc[i][j][k] = 0.0f;

    // issue loads for ks into buffer buf
    auto issue = [&](int ks, int buf) {
        uint32_t bo = buf * BUF_SZ;
        const char* sa_h = srcAh + ks * 64;
        const char* sa_l = srcAl + ks * 64;
#pragma unroll
        for (int c = 0; c < 4; c++) {
            CP16(dA + bo + c * 16,        sa_h + c * 16);
            CP16(dA + bo + A_PL + c * 16, sa_l + c * 16);
        }
        const char* sb_h = srcBh + ks * 64 + bch * 16;
        const char* sb_l = srcBl + ks * 64 + bch * 16;
#pragma unroll
        for (int c = 0; c < 2; c++) {
            CP16(dB + bo + c * 16,        sb_h + c * 16);
            CP16(dB + bo + B_PL + c * 16, sb_l + c * 16);
        }
    };

    issue(0, 0);
    CP_COMMIT();

#pragma unroll 1
    for (int ks = 0; ks < 8; ks++) {
        CP_WAIT0();
        __syncthreads();
        if (ks < 7) { issue(ks + 1, (ks + 1) & 1); CP_COMMIT(); }
        uint32_t bo = (ks & 1) * BUF_SZ;
#pragma unroll
        for (int kk = 0; kk < 2; kk++) {
            uint32_t ko = bo + kk * 32;
            uint32_t a_h[4][4], a_l[4][4];
#pragma unroll
            for (int mt = 0; mt < 4; mt++) {
                LDSM_X4(a_h[mt], aAddr[mt] + ko);
                LDSM_X4(a_l[mt], aAddr[mt] + ko + A_PL);
            }
            uint32_t b_h[4][4], b_l[4][4];
#pragma unroll
            for (int bt = 0; bt < 4; bt++) {
                LDSM_X4(b_h[bt], bAddr[bt] + ko);
                LDSM_X4(b_l[bt], bAddr[bt] + ko + B_PL);
            }
#pragma unroll
            for (int mt = 0; mt < 4; mt++)
#pragma unroll
                for (int nt = 0; nt < 8; nt++) {
                    uint32_t* bh = &b_h[nt >> 1][(nt & 1) * 2];
                    uint32_t* bl = &b_l[nt >> 1][(nt & 1) * 2];
                    MMA16816(acc[mt][nt], a_h[mt], bh);
                    MMA16816(acc[mt][nt], a_h[mt], bl);
                    MMA16816(acc[mt][nt], a_l[mt], bh);
                }
        }
    }

    // ---- epilogue ----
#pragma unroll
    for (int mt = 0; mt < 4; mt++) {
        int r0 = m0 + wm * 64 + mt * 16 + (lane >> 2);
        float rb0 = 0.f, rb1 = 0.f;
        if (ROWBIAS) { rb0 = bias[r0]; rb1 = bias[r0 + 8]; }
#pragma unroll
        for (int nt = 0; nt < 8; nt++) {
            int col = n0 + wn * 64 + nt * 8 + (lane & 3) * 2;
            float cb0 = 0.f, cb1 = 0.f;
            if (!ROWBIAS) { cb0 = bias[col]; cb1 = bias[col + 1]; }
            float* p = C + (size_t)r0 * ldc + col;
            float2 v;
            v.x = acc[mt][nt][0] + (ROWBIAS ? rb0 : cb0);
            v.y = acc[mt][nt][1] + (ROWBIAS ? rb0 : cb1);
            *(float2*)p = v;
            v.x = acc[mt][nt][2] + (ROWBIAS ? rb1 : cb0);
            v.y = acc[mt][nt][3] + (ROWBIAS ? rb1 : cb1);
            *(float2*)(p + (size_t)8 * ldc) = v;
        }
    }
}

// ---------------- attention: gather projected K/V rows, 9-tap softmax ----------------
__global__ __launch_bounds__(256)
void attn_kernel(const float* __restrict__ QKV, const int* __restrict__ idx,
                 __nv_bfloat16* __restrict__ OUTh, __nv_bfloat16* __restrict__ OUTl)
{
    int p0   = blockIdx.x << 5;
    int warp = threadIdx.x >> 5;
    int lane = threadIdx.x & 31;
    const float scale = 0.17677669529663687f;  // 1/sqrt(32)

#pragma unroll 1
    for (int task = warp; task < 256; task += 8) {
        int p  = task >> 3;
        int h  = task & 7;
        int pg = p0 + p;
        const int* ip = idx + pg * 9;
        int r[9];
#pragma unroll
        for (int t = 0; t < 9; t++) r[t] = ip[t];
        int cb = h * 32 + lane;
        float qd = QKV[(size_t)pg * 768 + cb];
        float kv[9], vv[9];
#pragma unroll
        for (int t = 0; t < 9; t++) kv[t] = QKV[(size_t)r[t] * 768 + 256 + cb];
#pragma unroll
        for (int t = 0; t < 9; t++) vv[t] = QKV[(size_t)r[t] * 768 + 512 + cb];
        float lg[9];
#pragma unroll
        for (int t = 0; t < 9; t++) {
            float prod = qd * kv[t];
#pragma unroll
            for (int off = 16; off > 0; off >>= 1)
                prod += __shfl_xor_sync(0xffffffffu, prod, off);
            lg[t] = prod * scale;
        }
        float mx = lg[0];
#pragma unroll
        for (int t = 1; t < 9; t++) mx = fmaxf(mx, lg[t]);
        float den = 0.0f, e[9];
#pragma unroll
        for (int t = 0; t < 9; t++) { e[t] = __expf(lg[t] - mx); den += e[t]; }
        float inv = 1.0f / den;
        float o = 0.0f;
#pragma unroll
        for (int t = 0; t < 9; t++) o += e[t] * vv[t];
        float val = o * inv;
        __nv_bfloat16 hi = __float2bfloat16(val);
        size_t oi = (size_t)pg * 256 + cb;
        OUTh[oi] = hi;
        OUTl[oi] = __float2bfloat16(val - __bfloat162float(hi));
    }
}

// ---------------- launch ----------------
extern "C" void kernel_launch(void* const* d_in, const int* in_sizes, int n_in,
                              void* d_out, int out_size)
{
    const float* x   = (const float*)d_in[0];
    const float* grd = (const float*)d_in[1];
    const float* wq  = (const float*)d_in[2];
    const float* bq  = (const float*)d_in[3];
    const float* wk  = (const float*)d_in[4];
    const float* bk  = (const float*)d_in[5];
    const float* wv  = (const float*)d_in[6];
    const float* bv  = (const float*)d_in[7];
    const float* wo  = (const float*)d_in[8];
    const float* bo  = (const float*)d_in[9];
    float* y = (float*)d_out;

    __nv_bfloat16 *XTh, *XTl, *Wh, *Wl, *OUTh, *OUTl;
    float *QKV, *bqkv;
    int* idx;
    cudaGetSymbolAddress((void**)&XTh,  g_XTh);
    cudaGetSymbolAddress((void**)&XTl,  g_XTl);
    cudaGetSymbolAddress((void**)&idx,  g_idx);
    cudaGetSymbolAddress((void**)&Wh,   g_Wh);
    cudaGetSymbolAddress((void**)&Wl,   g_Wl);
    cudaGetSymbolAddress((void**)&QKV,  g_QKV);
    cudaGetSymbolAddress((void**)&bqkv, g_bqkv);
    cudaGetSymbolAddress((void**)&OUTh, g_OUTh);
    cudaGetSymbolAddress((void**)&OUTl, g_OUTl);

    cudaFuncSetAttribute(hmma_gemm<false>, cudaFuncAttributeMaxDynamicSharedMemorySize, SMEM_SZ);
    cudaFuncSetAttribute(hmma_gemm<true >, cudaFuncAttributeMaxDynamicSharedMemorySize, SMEM_SZ);

    // 1) gather indices
    idx_kernel<<<NSAMP / 256, 256>>>(grd, idx);

    // 2) x -> XT bf16 hi/lo ; all weights + bias in one prep kernel
    transpose_conv<<<dim3(HW / 32, CC / 32), dim3(32, 8)>>>(x, XTh, XTl);
    prep_weights<<<(4 * CC * CC + 768 + 255) / 256, 256>>>(
        wq, wk, wv, wo, bq, bk, bv, Wh, Wl, bqkv);

    // 3) fused QKV projection over distinct pixels (project-then-gather)
    hmma_gemm<false><<<dim3(6, HW / 256), 256, SMEM_SZ>>>(
        XTh, XTl, Wh, Wl, bqkv, QKV, 768);

    // 4) attention with gathered projected rows -> OUT bf16 hi/lo [p][c]
    attn_kernel<<<HW / 32, 256>>>(QKV, idx, OUTh, OUTl);

    // 5) y[o][p] = wo[o][c] * OUT[p][c]^T + bo[o]  (M=256 wo rows, N=HW)
    hmma_gemm<true><<<dim3(HW / 128, 1), 256, SMEM_SZ>>>(
        Wh + 3 * CC * CC, Wl + 3 * CC * CC, OUTh, OUTl, bo, y, HW);
}

// round 6
// speedup vs baseline: 1.1455x; 1.1455x over previous
#include <cuda_runtime.h>
#include <cuda_bf16.h>
#include <cstdint>

// ---------------- problem constants ----------------
#define HH 128
#define WW 256
#define HW (HH*WW)          // 32768
#define CC 256
#define NSAMP (HW*9)        // 294912

// ---------------- static device scratch ----------------
__device__ __nv_bfloat16 g_XTh[(size_t)HW*CC];
__device__ __nv_bfloat16 g_XTl[(size_t)HW*CC];
__device__ int           g_idx[NSAMP];
__device__ __nv_bfloat16 g_Wh[4*CC*CC];   // q,k,v,o (q|k|v rows = fused B)
__device__ __nv_bfloat16 g_Wl[4*CC*CC];
__device__ float         g_bqkv[3*CC];
__device__ float         g_QKV[(size_t)HW*3*CC];   // [pixel][768] = Q|K|V
__device__ __nv_bfloat16 g_OUTh[(size_t)HW*CC];
__device__ __nv_bfloat16 g_OUTl[(size_t)HW*CC];

// ---------------- helpers ----------------
__device__ __forceinline__ uint32_t smem_u32(const void* p) {
    uint32_t a;
    asm("{ .reg .u64 t; cvta.to.shared.u64 t, %1; cvt.u32.u64 %0, t; }" : "=r"(a) : "l"(p));
    return a;
}
#define LDSM_X4(r, a) \
    asm volatile("ldmatrix.sync.aligned.m8n8.x4.shared.b16 {%0,%1,%2,%3}, [%4];" \
        : "=r"((r)[0]), "=r"((r)[1]), "=r"((r)[2]), "=r"((r)[3]) : "r"(a))

#define MMA16816(d, a, b) \
    asm volatile("mma.sync.aligned.m16n8k16.row.col.f32.bf16.bf16.f32 " \
        "{%0,%1,%2,%3}, {%4,%5,%6,%7}, {%8,%9}, {%0,%1,%2,%3};" \
        : "+f"((d)[0]), "+f"((d)[1]), "+f"((d)[2]), "+f"((d)[3]) \
        : "r"((a)[0]), "r"((a)[1]), "r"((a)[2]), "r"((a)[3]), "r"((b)[0]), "r"((b)[1]))

#define CP16(dst, src) \
    asm volatile("cp.async.cg.shared.global [%0], [%1], 16;" :: "r"(dst), "l"(src))
#define CP_COMMIT() asm volatile("cp.async.commit_group;")
#define CP_WAIT0()  asm volatile("cp.async.wait_group 0;")

// SMEM layout (bytes), per buffer: A_hi(128x80) A_lo B_hi(128x80) B_lo
#define LDS_ROW 80
#define PL      (128*LDS_ROW)        // 10240 per plane
#define BUF_SZ  (4*PL)               // 40960 per buffer
#define B_OFF   (2*PL)               // 20480
#define SMEM_SZ (2*BUF_SZ)           // 81920

// ---------------- index computation ----------------
__global__ void idx_kernel(const float* __restrict__ grid, int* __restrict__ idx)
{
    int s = blockIdx.x * 256 + threadIdx.x;
    if (s >= NSAMP) return;
    int p  = s / 9;
    int t  = s - p * 9;
    int h  = p >> 8;
    int w  = p & 255;
    int kh = t / 3;
    int kw = t - kh * 3;
    const float* g = grid + ((size_t)(h * 3 + kh) * 768 + (w * 3 + kw)) * 2;
    float fx = rintf(((g[0] + 1.0f) * 0.5f) * 255.0f);
    float fy = rintf(((g[1] + 1.0f) * 0.5f) * 127.0f);
    int ix = (int)fminf(fmaxf(fx, 0.0f), 255.0f);
    int iy = (int)fminf(fmaxf(fy, 0.0f), 127.0f);
    idx[s] = iy * WW + ix;
}

// ---------------- transpose x[C][HW] -> XTh/XTl [HW][C] ----------------
__global__ void transpose_conv(const float* __restrict__ in,
                               __nv_bfloat16* __restrict__ oh, __nv_bfloat16* __restrict__ ol)
{
    __shared__ float tile[32][33];
    int c0 = blockIdx.x * 32;   // hw
    int r0 = blockIdx.y * 32;   // channel
    int tx = threadIdx.x, ty = threadIdx.y;
#pragma unroll
    for (int i = 0; i < 32; i += 8)
        tile[ty + i][tx] = in[(size_t)(r0 + ty + i) * HW + c0 + tx];
    __syncthreads();
#pragma unroll
    for (int i = 0; i < 32; i += 8) {
        float v = tile[tx][ty + i];
        __nv_bfloat16 h = __float2bfloat16(v);
        size_t o = (size_t)(c0 + ty + i) * CC + r0 + tx;
        oh[o] = h;
        ol[o] = __float2bfloat16(v - __bfloat162float(h));
    }
}

// ---------------- fused weight/bias prep ----------------
__global__ void prep_weights(const float* __restrict__ wq, const float* __restrict__ wk,
                             const float* __restrict__ wv, const float* __restrict__ wo,
                             const float* __restrict__ bq, const float* __restrict__ bk,
                             const float* __restrict__ bv,
                             __nv_bfloat16* __restrict__ Wh, __nv_bfloat16* __restrict__ Wl,
                             float* __restrict__ bqkv)
{
    int i = blockIdx.x * 256 + threadIdx.x;
    if (i < 4 * CC * CC) {
        int m = i >> 16;
        int j = i & 0xFFFF;
        const float* src = (m == 0) ? wq : (m == 1) ? wk : (m == 2) ? wv : wo;
        float v = src[j];
        __nv_bfloat16 hi = __float2bfloat16(v);
        Wh[i] = hi;
        Wl[i] = __float2bfloat16(v - __bfloat162float(hi));
    } else {
        int j = i - 4 * CC * CC;
        if (j < 768)
            bqkv[j] = (j < 256) ? bq[j] : ((j < 512) ? bk[j - 256] : bv[j - 512]);
    }
}

// ---------------- HMMA bf16-split GEMM, CTA 128x128, warp 64x32, 2 CTAs/SM ----------------
// C[M][N] = A[M][256] * B[N][256]^T + bias.  ROWBIAS: bias per m, else per n.
template<bool ROWBIAS>
__global__ __launch_bounds__(256, 2)
void hmma_gemm(const __nv_bfloat16* __restrict__ Ah, const __nv_bfloat16* __restrict__ Al,
               const __nv_bfloat16* __restrict__ Bh, const __nv_bfloat16* __restrict__ Bl,
               const float* __restrict__ bias, float* __restrict__ C, int ldc)
{
    extern __shared__ __align__(16) char sm[];
    uint32_t smb = smem_u32(sm);
    int tid = threadIdx.x;
    int wid = tid >> 5, lane = tid & 31;
    int wm = wid >> 2, wn = wid & 3;
    int m0 = blockIdx.y * 128, n0 = blockIdx.x * 128;

    // cp.async: 2 threads per row, 2x16B chunks each, per plane per ks(32k)
    int row = tid >> 1, ch = (tid & 1) * 2;
    const char* srcAh = (const char*)(Ah + (size_t)(m0 + row) * 256) + ch * 16;
    const char* srcAl = (const char*)(Al + (size_t)(m0 + row) * 256) + ch * 16;
    const char* srcBh = (const char*)(Bh + (size_t)(n0 + row) * 256) + ch * 16;
    const char* srcBl = (const char*)(Bl + (size_t)(n0 + row) * 256) + ch * 16;
    uint32_t dst = smb + row * LDS_ROW + ch * 16;

    // ldmatrix fragment addresses (buffer 0, hi planes)
    uint32_t aAddr[4], bAddr[2];
#pragma unroll
    for (int mt = 0; mt < 4; mt++)
        aAddr[mt] = smb + (wm * 64 + mt * 16 + (lane & 15)) * LDS_ROW + ((lane >> 4) * 16);
#pragma unroll
    for (int bt = 0; bt < 2; bt++)
        bAddr[bt] = smb + B_OFF + (wn * 32 + bt * 16 + ((lane >> 4) & 1) * 8 + (lane & 7)) * LDS_ROW
                  + (((lane >> 3) & 1) * 16);

    float acc[4][4][4];
#pragma unroll
    for (int i = 0; i < 4; i++)
#pragma unroll
        for (int j = 0; j < 4; j++)
#pragma unroll
            for (int k = 0; k < 4; k++) acc[i][j][k] = 0.0f;

    auto issue = [&](int ks, int buf) {
        uint32_t bo = buf * BUF_SZ;
#pragma unroll
        for (int c = 0; c < 2; c++) {
            CP16(dst + bo + c * 16,          srcAh + ks * 64 + c * 16);
            CP16(dst + bo + PL + c * 16,     srcAl + ks * 64 + c * 16);
            CP16(dst + bo + B_OFF + c * 16,      srcBh + ks * 64 + c * 16);
            CP16(dst + bo + B_OFF + PL + c * 16, srcBl + ks * 64 + c * 16);
        }
    };

    issue(0, 0);
    CP_COMMIT();

#pragma unroll 1
    for (int ks = 0; ks < 8; ks++) {
        CP_WAIT0();
        __syncthreads();
        if (ks < 7) { issue(ks + 1, (ks + 1) & 1); CP_COMMIT(); }
        uint32_t bo = (ks & 1) * BUF_SZ;
#pragma unroll
        for (int kk = 0; kk < 2; kk++) {
            uint32_t ko = bo + kk * 32;
            // load hi A frags + both B frags
            uint32_t a_h[4][4];
#pragma unroll
            for (int mt = 0; mt < 4; mt++) LDSM_X4(a_h[mt], aAddr[mt] + ko);
            uint32_t b_h[2][4], b_l[2][4];
#pragma unroll
            for (int bt = 0; bt < 2; bt++) {
                LDSM_X4(b_h[bt], bAddr[bt] + ko);
                LDSM_X4(b_l[bt], bAddr[bt] + ko + PL);
            }
            // pass 1: a_h * b_h   (16 independent MMAs)
#pragma unroll
            for (int mt = 0; mt < 4; mt++)
#pragma unroll
                for (int nt = 0; nt < 4; nt++)
                    MMA16816(acc[mt][nt], a_h[mt], (&b_h[nt >> 1][(nt & 1) * 2]));
            // pass 2: a_h * b_l
#pragma unroll
            for (int mt = 0; mt < 4; mt++)
#pragma unroll
                for (int nt = 0; nt < 4; nt++)
                    MMA16816(acc[mt][nt], a_h[mt], (&b_l[nt >> 1][(nt & 1) * 2]));
            // load lo A frags (a_h now dead), pass 3: a_l * b_h
            uint32_t a_l[4][4];
#pragma unroll
            for (int mt = 0; mt < 4; mt++) LDSM_X4(a_l[mt], aAddr[mt] + ko + PL);
#pragma unroll
            for (int mt = 0; mt < 4; mt++)
#pragma unroll
                for (int nt = 0; nt < 4; nt++)
                    MMA16816(acc[mt][nt], a_l[mt], (&b_h[nt >> 1][(nt & 1) * 2]));
        }
    }

    // ---- epilogue ----
#pragma unroll
    for (int mt = 0; mt < 4; mt++) {
        int r0 = m0 + wm * 64 + mt * 16 + (lane >> 2);
        float rb0 = 0.f, rb1 = 0.f;
        if (ROWBIAS) { rb0 = bias[r0]; rb1 = bias[r0 + 8]; }
#pragma unroll
        for (int nt = 0; nt < 4; nt++) {
            int col = n0 + wn * 32 + nt * 8 + (lane & 3) * 2;
            float cb0 = 0.f, cb1 = 0.f;
            if (!ROWBIAS) { cb0 = bias[col]; cb1 = bias[col + 1]; }
            float* p = C + (size_t)r0 * ldc + col;
            float2 v;
            v.x = acc[mt][nt][0] + (ROWBIAS ? rb0 : cb0);
            v.y = acc[mt][nt][1] + (ROWBIAS ? rb0 : cb1);
            *(float2*)p = v;
            v.x = acc[mt][nt][2] + (ROWBIAS ? rb1 : cb0);
            v.y = acc[mt][nt][3] + (ROWBIAS ? rb1 : cb1);
            *(float2*)(p + (size_t)8 * ldc) = v;
        }
    }
}

// ---------------- attention: gather projected K/V rows, 9-tap softmax ----------------
__global__ __launch_bounds__(256)
void attn_kernel(const float* __restrict__ QKV, const int* __restrict__ idx,
                 __nv_bfloat16* __restrict__ OUTh, __nv_bfloat16* __restrict__ OUTl)
{
    int p0   = blockIdx.x << 5;
    int warp = threadIdx.x >> 5;
    int lane = threadIdx.x & 31;
    const float scale = 0.17677669529663687f;  // 1/sqrt(32)

#pragma unroll 1
    for (int task = warp; task < 256; task += 8) {
        int p  = task >> 3;
        int h  = task & 7;
        int pg = p0 + p;
        const int* ip = idx + pg * 9;
        int r[9];
#pragma unroll
        for (int t = 0; t < 9; t++) r[t] = ip[t];
        int cb = h * 32 + lane;
        float qd = QKV[(size_t)pg * 768 + cb];
        float kv[9], vv[9];
#pragma unroll
        for (int t = 0; t < 9; t++) kv[t] = QKV[(size_t)r[t] * 768 + 256 + cb];
#pragma unroll
        for (int t = 0; t < 9; t++) vv[t] = QKV[(size_t)r[t] * 768 + 512 + cb];
        float lg[9];
#pragma unroll
        for (int t = 0; t < 9; t++) {
            float prod = qd * kv[t];
#pragma unroll
            for (int off = 16; off > 0; off >>= 1)
                prod += __shfl_xor_sync(0xffffffffu, prod, off);
            lg[t] = prod * scale;
        }
        float mx = lg[0];
#pragma unroll
        for (int t = 1; t < 9; t++) mx = fmaxf(mx, lg[t]);
        float den = 0.0f, e[9];
#pragma unroll
        for (int t = 0; t < 9; t++) { e[t] = __expf(lg[t] - mx); den += e[t]; }
        float inv = 1.0f / den;
        float o = 0.0f;
#pragma unroll
        for (int t = 0; t < 9; t++) o += e[t] * vv[t];
        float val = o * inv;
        __nv_bfloat16 hi = __float2bfloat16(val);
        size_t oi = (size_t)pg * 256 + cb;
        OUTh[oi] = hi;
        OUTl[oi] = __float2bfloat16(val - __bfloat162float(hi));
    }
}

// ---------------- launch ----------------
extern "C" void kernel_launch(void* const* d_in, const int* in_sizes, int n_in,
                              void* d_out, int out_size)
{
    const float* x   = (const float*)d_in[0];
    const float* grd = (const float*)d_in[1];
    const float* wq  = (const float*)d_in[2];
    const float* bq  = (const float*)d_in[3];
    const float* wk  = (const float*)d_in[4];
    const float* bk  = (const float*)d_in[5];
    const float* wv  = (const float*)d_in[6];
    const float* bv  = (const float*)d_in[7];
    const float* wo  = (const float*)d_in[8];
    const float* bo  = (const float*)d_in[9];
    float* y = (float*)d_out;

    __nv_bfloat16 *XTh, *XTl, *Wh, *Wl, *OUTh, *OUTl;
    float *QKV, *bqkv;
    int* idx;
    cudaGetSymbolAddress((void**)&XTh,  g_XTh);
    cudaGetSymbolAddress((void**)&XTl,  g_XTl);
    cudaGetSymbolAddress((void**)&idx,  g_idx);
    cudaGetSymbolAddress((void**)&Wh,   g_Wh);
    cudaGetSymbolAddress((void**)&Wl,   g_Wl);
    cudaGetSymbolAddress((void**)&QKV,  g_QKV);
    cudaGetSymbolAddress((void**)&bqkv, g_bqkv);
    cudaGetSymbolAddress((void**)&OUTh, g_OUTh);
    cudaGetSymbolAddress((void**)&OUTl, g_OUTl);

    cudaFuncSetAttribute(hmma_gemm<false>, cudaFuncAttributeMaxDynamicSharedMemorySize, SMEM_SZ);
    cudaFuncSetAttribute(hmma_gemm<true >, cudaFuncAttributeMaxDynamicSharedMemorySize, SMEM_SZ);

    // 1) gather indices
    idx_kernel<<<NSAMP / 256, 256>>>(grd, idx);

    // 2) x -> XT bf16 hi/lo ; weights + bias prep
    transpose_conv<<<dim3(HW / 32, CC / 32), dim3(32, 8)>>>(x, XTh, XTl);
    prep_weights<<<(4 * CC * CC + 768 + 255) / 256, 256>>>(
        wq, wk, wv, wo, bq, bk, bv, Wh, Wl, bqkv);

    // 3) fused QKV projection over distinct pixels (project-then-gather)
    hmma_gemm<false><<<dim3(6, HW / 128), 256, SMEM_SZ>>>(
        XTh, XTl, Wh, Wl, bqkv, QKV, 768);

    // 4) attention with gathered projected rows -> OUT bf16 hi/lo [p][c]
    attn_kernel<<<HW / 32, 256>>>(QKV, idx, OUTh, OUTl);

    // 5) y[o][p] = wo[o][c] * OUT[p][c]^T + bo[o]
    hmma_gemm<true><<<dim3(HW / 128, CC / 128), 256, SMEM_SZ>>>(
        Wh + 3 * CC * CC, Wl + 3 * CC * CC, OUTh, OUTl, bo, y, HW);
}

// round 7
// speedup vs baseline: 1.2286x; 1.0726x over previous
#include <cuda_runtime.h>
#include <cuda_fp16.h>
#include <cstdint>

// ---------------- problem constants ----------------
#define HH 128
#define WW 256
#define HW (HH*WW)          // 32768
#define CC 256
#define NSAMP (HW*9)        // 294912

// ---------------- static device scratch ----------------
__device__ __half g_XT2[(size_t)HW*512];     // [pixel][512] = x_hi | x_lo   (fp16)
__device__ int    g_idx[NSAMP];
__device__ __half g_W2[(size_t)1024*512];    // rows 0-767 qkv, 768-1023 wo; [row][512] = w_hi | w_hi
__device__ float  g_bqkv[3*CC];
__device__ float  g_QKV[(size_t)HW*3*CC];    // [pixel][768] = Q|K|V
__device__ __half g_OUT2[(size_t)HW*512];    // [pixel][512] = out_hi | out_lo

// ---------------- helpers ----------------
__device__ __forceinline__ uint32_t smem_u32(const void* p) {
    uint32_t a;
    asm("{ .reg .u64 t; cvta.to.shared.u64 t, %1; cvt.u32.u64 %0, t; }" : "=r"(a) : "l"(p));
    return a;
}
#define LDSM_X4(r, a) \
    asm volatile("ldmatrix.sync.aligned.m8n8.x4.shared.b16 {%0,%1,%2,%3}, [%4];" \
        : "=r"((r)[0]), "=r"((r)[1]), "=r"((r)[2]), "=r"((r)[3]) : "r"(a))

#define MMA16816(d, a, b) \
    asm volatile("mma.sync.aligned.m16n8k16.row.col.f32.f16.f16.f32 " \
        "{%0,%1,%2,%3}, {%4,%5,%6,%7}, {%8,%9}, {%0,%1,%2,%3};" \
        : "+f"((d)[0]), "+f"((d)[1]), "+f"((d)[2]), "+f"((d)[3]) \
        : "r"((a)[0]), "r"((a)[1]), "r"((a)[2]), "r"((a)[3]), "r"((b)[0]), "r"((b)[1]))

#define CP16(dst, src) \
    asm volatile("cp.async.cg.shared.global [%0], [%1], 16;" :: "r"(dst), "l"(src))
#define CP_COMMIT() asm volatile("cp.async.commit_group;")
#define CP_WAIT0()  asm volatile("cp.async.wait_group 0;")

// SMEM layout (bytes), per buffer: A(128x80) B(128x80)
#define LDS_ROW 80
#define PL      (128*LDS_ROW)        // 10240 per tile
#define BUF_SZ  (2*PL)               // 20480 per buffer
#define B_OFF   PL
#define SMEM_SZ (2*BUF_SZ)           // 40960

// ---------------- index computation ----------------
__global__ void idx_kernel(const float* __restrict__ grid, int* __restrict__ idx)
{
    int s = blockIdx.x * 256 + threadIdx.x;
    if (s >= NSAMP) return;
    int p  = s / 9;
    int t  = s - p * 9;
    int h  = p >> 8;
    int w  = p & 255;
    int kh = t / 3;
    int kw = t - kh * 3;
    const float* g = grid + ((size_t)(h * 3 + kh) * 768 + (w * 3 + kw)) * 2;
    float fx = rintf(((g[0] + 1.0f) * 0.5f) * 255.0f);
    float fy = rintf(((g[1] + 1.0f) * 0.5f) * 127.0f);
    int ix = (int)fminf(fmaxf(fx, 0.0f), 255.0f);
    int iy = (int)fminf(fmaxf(fy, 0.0f), 127.0f);
    idx[s] = iy * WW + ix;
}

// ---------------- transpose x[C][HW] -> XT2 [HW][512] = hi|lo fp16 ----------------
__global__ void transpose_conv(const float* __restrict__ in, __half* __restrict__ o2)
{
    __shared__ float tile[32][33];
    int c0 = blockIdx.x * 32;   // hw
    int r0 = blockIdx.y * 32;   // channel
    int tx = threadIdx.x, ty = threadIdx.y;
#pragma unroll
    for (int i = 0; i < 32; i += 8)
        tile[ty + i][tx] = in[(size_t)(r0 + ty + i) * HW + c0 + tx];
    __syncthreads();
#pragma unroll
    for (int i = 0; i < 32; i += 8) {
        float v = tile[tx][ty + i];
        __half h = __float2half_rn(v);
        size_t o = (size_t)(c0 + ty + i) * 512 + r0 + tx;
        o2[o]       = h;
        o2[o + 256] = __float2half_rn(v - __half2float(h));
    }
}

// ---------------- fused weight/bias prep: w_hi duplicated into both K halves ----------------
__global__ void prep_weights(const float* __restrict__ wq, const float* __restrict__ wk,
                             const float* __restrict__ wv, const float* __restrict__ wo,
                             const float* __restrict__ bq, const float* __restrict__ bk,
                             const float* __restrict__ bv,
                             __half* __restrict__ W2, float* __restrict__ bqkv)
{
    int i = blockIdx.x * 256 + threadIdx.x;
    if (i < 4 * CC * CC) {
        int m = i >> 16;
        int j = i & 0xFFFF;
        int row = j >> 8, col = j & 255;
        const float* src = (m == 0) ? wq : (m == 1) ? wk : (m == 2) ? wv : wo;
        __half h = __float2half_rn(src[j]);
        size_t d = ((size_t)(m * 256 + row)) * 512 + col;
        W2[d]       = h;
        W2[d + 256] = h;
    } else {
        int j = i - 4 * CC * CC;
        if (j < 768)
            bqkv[j] = (j < 256) ? bq[j] : ((j < 512) ? bk[j - 256] : bv[j - 512]);
    }
}

// ---------------- HMMA fp16 GEMM, K=512 folded, CTA 128x128, warp 64x32, 2 CTAs/SM ----------------
// C[M][N] = sum_k A[m][k]*B[n][k] + bias;  A,B are [row][512] fp16.
template<bool ROWBIAS>
__global__ __launch_bounds__(256, 2)
void hmma_gemm(const __half* __restrict__ A, const __half* __restrict__ B,
               const float* __restrict__ bias, float* __restrict__ C, int ldc)
{
    extern __shared__ __align__(16) char sm[];
    uint32_t smb = smem_u32(sm);
    int tid = threadIdx.x;
    int wid = tid >> 5, lane = tid & 31;
    int wm = wid >> 2, wn = wid & 3;
    int m0 = blockIdx.y * 128, n0 = blockIdx.x * 128;

    // cp.async: 2 threads per row, 2x16B chunks each, per ks(32k) slice
    int row = tid >> 1, ch = (tid & 1) * 2;
    const char* srcA = (const char*)(A + (size_t)(m0 + row) * 512) + ch * 16;
    const char* srcB = (const char*)(B + (size_t)(n0 + row) * 512) + ch * 16;
    uint32_t dst = smb + row * LDS_ROW + ch * 16;

    // ldmatrix fragment addresses (buffer 0)
    uint32_t aAddr[4], bAddr[2];
#pragma unroll
    for (int mt = 0; mt < 4; mt++)
        aAddr[mt] = smb + (wm * 64 + mt * 16 + (lane & 15)) * LDS_ROW + ((lane >> 4) * 16);
#pragma unroll
    for (int bt = 0; bt < 2; bt++)
        bAddr[bt] = smb + B_OFF + (wn * 32 + bt * 16 + ((lane >> 4) & 1) * 8 + (lane & 7)) * LDS_ROW
                  + (((lane >> 3) & 1) * 16);

    float acc[4][4][4];
#pragma unroll
    for (int i = 0; i < 4; i++)
#pragma unroll
        for (int j = 0; j < 4; j++)
#pragma unroll
            for (int k = 0; k < 4; k++) acc[i][j][k] = 0.0f;

    auto issue = [&](int ks, int buf) {
        uint32_t bo = buf * BUF_SZ;
#pragma unroll
        for (int c = 0; c < 2; c++) {
            CP16(dst + bo + c * 16,         srcA + ks * 64 + c * 16);
            CP16(dst + bo + B_OFF + c * 16, srcB + ks * 64 + c * 16);
        }
    };

    issue(0, 0);
    CP_COMMIT();

#pragma unroll 1
    for (int ks = 0; ks < 16; ks++) {          // 16 chunks x 32k = K 512
        CP_WAIT0();
        __syncthreads();
        if (ks < 15) { issue(ks + 1, (ks + 1) & 1); CP_COMMIT(); }
        uint32_t bo = (ks & 1) * BUF_SZ;
#pragma unroll
        for (int kk = 0; kk < 2; kk++) {
            uint32_t ko = bo + kk * 32;
            uint32_t a[4][4];
#pragma unroll
            for (int mt = 0; mt < 4; mt++) LDSM_X4(a[mt], aAddr[mt] + ko);
            uint32_t b[2][4];
#pragma unroll
            for (int bt = 0; bt < 2; bt++) LDSM_X4(b[bt], bAddr[bt] + ko);
#pragma unroll
            for (int mt = 0; mt < 4; mt++)
#pragma unroll
                for (int nt = 0; nt < 4; nt++)
                    MMA16816(acc[mt][nt], a[mt], (&b[nt >> 1][(nt & 1) * 2]));
        }
    }

    // ---- epilogue ----
#pragma unroll
    for (int mt = 0; mt < 4; mt++) {
        int r0 = m0 + wm * 64 + mt * 16 + (lane >> 2);
        float rb0 = 0.f, rb1 = 0.f;
        if (ROWBIAS) { rb0 = bias[r0]; rb1 = bias[r0 + 8]; }
#pragma unroll
        for (int nt = 0; nt < 4; nt++) {
            int col = n0 + wn * 32 + nt * 8 + (lane & 3) * 2;
            float cb0 = 0.f, cb1 = 0.f;
            if (!ROWBIAS) { cb0 = bias[col]; cb1 = bias[col + 1]; }
            float* p = C + (size_t)r0 * ldc + col;
            float2 v;
            v.x = acc[mt][nt][0] + (ROWBIAS ? rb0 : cb0);
            v.y = acc[mt][nt][1] + (ROWBIAS ? rb0 : cb1);
            *(float2*)p = v;
            v.x = acc[mt][nt][2] + (ROWBIAS ? rb1 : cb0);
            v.y = acc[mt][nt][3] + (ROWBIAS ? rb1 : cb1);
            *(float2*)(p + (size_t)8 * ldc) = v;
        }
    }
}

// ---------------- attention: gather projected K/V rows, 9-tap softmax ----------------
__global__ __launch_bounds__(256)
void attn_kernel(const float* __restrict__ QKV, const int* __restrict__ idx,
                 __half* __restrict__ OUT2)
{
    int p0   = blockIdx.x << 5;
    int warp = threadIdx.x >> 5;
    int lane = threadIdx.x & 31;
    const float scale = 0.17677669529663687f;  // 1/sqrt(32)

#pragma unroll 1
    for (int task = warp; task < 256; task += 8) {
        int p  = task >> 3;
        int h  = task & 7;
        int pg = p0 + p;
        const int* ip = idx + pg * 9;
        int r[9];
#pragma unroll
        for (int t = 0; t < 9; t++) r[t] = ip[t];
        int cb = h * 32 + lane;
        float qd = QKV[(size_t)pg * 768 + cb];
        float kv[9], vv[9];
#pragma unroll
        for (int t = 0; t < 9; t++) kv[t] = QKV[(size_t)r[t] * 768 + 256 + cb];
#pragma unroll
        for (int t = 0; t < 9; t++) vv[t] = QKV[(size_t)r[t] * 768 + 512 + cb];
        float lg[9];
#pragma unroll
        for (int t = 0; t < 9; t++) {
            float prod = qd * kv[t];
#pragma unroll
            for (int off = 16; off > 0; off >>= 1)
                prod += __shfl_xor_sync(0xffffffffu, prod, off);
            lg[t] = prod * scale;
        }
        float mx = lg[0];
#pragma unroll
        for (int t = 1; t < 9; t++) mx = fmaxf(mx, lg[t]);
        float den = 0.0f, e[9];
#pragma unroll
        for (int t = 0; t < 9; t++) { e[t] = __expf(lg[t] - mx); den += e[t]; }
        float inv = 1.0f / den;
        float o = 0.0f;
#pragma unroll
        for (int t = 0; t < 9; t++) o += e[t] * vv[t];
        float val = o * inv;
        __half hi = __float2half_rn(val);
        size_t oi = (size_t)pg * 512 + cb;
        OUT2[oi]       = hi;
        OUT2[oi + 256] = __float2half_rn(val - __half2float(hi));
    }
}

// ---------------- launch ----------------
extern "C" void kernel_launch(void* const* d_in, const int* in_sizes, int n_in,
                              void* d_out, int out_size)
{
    const float* x   = (const float*)d_in[0];
    const float* grd = (const float*)d_in[1];
    const float* wq  = (const float*)d_in[2];
    const float* bq  = (const float*)d_in[3];
    const float* wk  = (const float*)d_in[4];
    const float* bk  = (const float*)d_in[5];
    const float* wv  = (const float*)d_in[6];
    const float* bv  = (const float*)d_in[7];
    const float* wo  = (const float*)d_in[8];
    const float* bo  = (const float*)d_in[9];
    float* y = (float*)d_out;

    __half *XT2, *W2, *OUT2;
    float *QKV, *bqkv;
    int* idx;
    cudaGetSymbolAddress((void**)&XT2,  g_XT2);
    cudaGetSymbolAddress((void**)&idx,  g_idx);
    cudaGetSymbolAddress((void**)&W2,   g_W2);
    cudaGetSymbolAddress((void**)&QKV,  g_QKV);
    cudaGetSymbolAddress((void**)&bqkv, g_bqkv);
    cudaGetSymbolAddress((void**)&OUT2, g_OUT2);

    cudaFuncSetAttribute(hmma_gemm<false>, cudaFuncAttributeMaxDynamicSharedMemorySize, SMEM_SZ);
    cudaFuncSetAttribute(hmma_gemm<true >, cudaFuncAttributeMaxDynamicSharedMemorySize, SMEM_SZ);

    // 1) gather indices
    idx_kernel<<<NSAMP / 256, 256>>>(grd, idx);

    // 2) x -> XT2 (hi|lo fp16); weights hi duplicated + bias concat
    transpose_conv<<<dim3(HW / 32, CC / 32), dim3(32, 8)>>>(x, XT2);
    prep_weights<<<(4 * CC * CC + 768 + 255) / 256, 256>>>(
        wq, wk, wv, wo, bq, bk, bv, W2, bqkv);

    // 3) fused QKV projection over distinct pixels (project-then-gather), K=512 folded
    hmma_gemm<false><<<dim3(6, HW / 128), 256, SMEM_SZ>>>(
        XT2, W2, bqkv, QKV, 768);

    // 4) attention with gathered projected rows -> OUT2 (hi|lo fp16)
    attn_kernel<<<HW / 32, 256>>>(QKV, idx, OUT2);

    // 5) y[o][p] = wo[o][c] * OUT[p][c]^T + bo[o]
    hmma_gemm<true><<<dim3(HW / 128, CC / 128), 256, SMEM_SZ>>>(
        W2 + (size_t)768 * 512, OUT2, bo, y, HW);
}

// round 8
// speedup vs baseline: 1.3479x; 1.0971x over previous
#include <cuda_runtime.h>
#include <cuda_fp16.h>
#include <cstdint>

// ---------------- problem constants ----------------
#define HH 128
#define WW 256
#define HW (HH*WW)          // 32768
#define CC 256
#define NSAMP (HW*9)        // 294912

// ---------------- static device scratch ----------------
__device__ __half g_XT2[(size_t)HW*512];     // [pixel][512] = x_hi | x_lo  (fp16)
__device__ int    g_idx[NSAMP];
__device__ __half g_W[(size_t)1024*256];     // rows 0-767 qkv, 768-1023 wo (fp16 hi)
__device__ float  g_bqkv[3*CC];
__device__ float  g_QKV[(size_t)HW*3*CC];    // [pixel][768] = Q|K|V
__device__ __half g_OUT2[(size_t)HW*512];    // [pixel][512] = out_hi | out_lo

// ---------------- helpers ----------------
__device__ __forceinline__ uint32_t smem_u32(const void* p) {
    uint32_t a;
    asm("{ .reg .u64 t; cvta.to.shared.u64 t, %1; cvt.u32.u64 %0, t; }" : "=r"(a) : "l"(p));
    return a;
}
#define LDSM_X4(r, a) \
    asm volatile("ldmatrix.sync.aligned.m8n8.x4.shared.b16 {%0,%1,%2,%3}, [%4];" \
        : "=r"((r)[0]), "=r"((r)[1]), "=r"((r)[2]), "=r"((r)[3]) : "r"(a))

#define MMA16816(d, a, b) \
    asm volatile("mma.sync.aligned.m16n8k16.row.col.f32.f16.f16.f32 " \
        "{%0,%1,%2,%3}, {%4,%5,%6,%7}, {%8,%9}, {%0,%1,%2,%3};" \
        : "+f"((d)[0]), "+f"((d)[1]), "+f"((d)[2]), "+f"((d)[3]) \
        : "r"((a)[0]), "r"((a)[1]), "r"((a)[2]), "r"((a)[3]), "r"((b)[0]), "r"((b)[1]))

#define CP16(dst, src) \
    asm volatile("cp.async.cg.shared.global [%0], [%1], 16;" :: "r"(dst), "l"(src))
#define CP_COMMIT() asm volatile("cp.async.commit_group;")
#define CP_WAIT1()  asm volatile("cp.async.wait_group 1;")

// SMEM: 3 stages x 3 planes(128x80B)
#define LDS_ROW 80
#define PL      (128*LDS_ROW)        // 10240 per plane
#define STG_SZ  (3*PL)               // 30720 per stage
#define SMEM_SZ (3*STG_SZ)           // 92160

// ---------------- index computation ----------------
__global__ void idx_kernel(const float* __restrict__ grid, int* __restrict__ idx)
{
    int s = blockIdx.x * 256 + threadIdx.x;
    if (s >= NSAMP) return;
    int p  = s / 9;
    int t  = s - p * 9;
    int h  = p >> 8;
    int w  = p & 255;
    int kh = t / 3;
    int kw = t - kh * 3;
    const float* g = grid + ((size_t)(h * 3 + kh) * 768 + (w * 3 + kw)) * 2;
    float fx = rintf(((g[0] + 1.0f) * 0.5f) * 255.0f);
    float fy = rintf(((g[1] + 1.0f) * 0.5f) * 127.0f);
    int ix = (int)fminf(fmaxf(fx, 0.0f), 255.0f);
    int iy = (int)fminf(fmaxf(fy, 0.0f), 127.0f);
    idx[s] = iy * WW + ix;
}

// ---------------- transpose x[C][HW] -> XT2 [HW][512] = hi|lo fp16 ----------------
__global__ void transpose_conv(const float* __restrict__ in, __half* __restrict__ o2)
{
    __shared__ float tile[32][33];
    int c0 = blockIdx.x * 32;   // hw
    int r0 = blockIdx.y * 32;   // channel
    int tx = threadIdx.x, ty = threadIdx.y;
#pragma unroll
    for (int i = 0; i < 32; i += 8)
        tile[ty + i][tx] = in[(size_t)(r0 + ty + i) * HW + c0 + tx];
    __syncthreads();
#pragma unroll
    for (int i = 0; i < 32; i += 8) {
        float v = tile[tx][ty + i];
        __half h = __float2half_rn(v);
        size_t o = (size_t)(c0 + ty + i) * 512 + r0 + tx;
        o2[o]       = h;
        o2[o + 256] = __float2half_rn(v - __half2float(h));
    }
}

// ---------------- fused weight/bias prep ----------------
__global__ void prep_weights(const float* __restrict__ wq, const float* __restrict__ wk,
                             const float* __restrict__ wv, const float* __restrict__ wo,
                             const float* __restrict__ bq, const float* __restrict__ bk,
                             const float* __restrict__ bv,
                             __half* __restrict__ W, float* __restrict__ bqkv)
{
    int i = blockIdx.x * 256 + threadIdx.x;
    if (i < 4 * CC * CC) {
        int m = i >> 16;
        int j = i & 0xFFFF;
        const float* src = (m == 0) ? wq : (m == 1) ? wk : (m == 2) ? wv : wo;
        W[i] = __float2half_rn(src[j]);
    } else {
        int j = i - 4 * CC * CC;
        if (j < 768)
            bqkv[j] = (j < 256) ? bq[j] : ((j < 512) ? bk[j - 256] : bv[j - 512]);
    }
}

// ---------------- HMMA fp16 2-pass GEMM, K=256, B-reuse, 3-stage cp.async ----------------
// SPLITA: A rows are [512] = hi|lo, B rows [256]: acc += A_hi*B + A_lo*B
// else  : A rows [256],  B rows [512] = hi|lo:   acc += A*B_hi + A*B_lo
// C[M][N] (+bias per-m if ROWBIAS else per-n).  CTA 128x128, warp 64x32.
template<bool ROWBIAS, bool SPLITA>
__global__ __launch_bounds__(256, 2)
void hmma_gemm(const __half* __restrict__ A, const __half* __restrict__ B,
               const float* __restrict__ bias, float* __restrict__ C, int ldc)
{
    extern __shared__ __align__(16) char sm[];
    uint32_t smb = smem_u32(sm);
    int tid = threadIdx.x;
    int wid = tid >> 5, lane = tid & 31;
    int wm = wid >> 2, wn = wid & 3;
    int m0 = blockIdx.y * 128, n0 = blockIdx.x * 128;

    const int strideA = SPLITA ? 512 : 256;   // halves per row
    const int strideB = SPLITA ? 256 : 512;

    // cp.async: 2 threads per row, 2x16B chunks each, per ks(32k) slice
    int row = tid >> 1, ch = (tid & 1) * 2;
    const char* srcA = (const char*)(A + (size_t)(m0 + row) * strideA) + ch * 16;
    const char* srcB = (const char*)(B + (size_t)(n0 + row) * strideB) + ch * 16;
    uint32_t dst = smb + row * LDS_ROW + ch * 16;

    // plane layout per stage: SPLITA: {A_hi, A_lo, B} ; SPLITB: {A, B_hi, B_lo}
    // ldmatrix fragment addresses (stage 0)
    uint32_t aAddr[4], bAddr[2];
#pragma unroll
    for (int mt = 0; mt < 4; mt++)
        aAddr[mt] = smb + (wm * 64 + mt * 16 + (lane & 15)) * LDS_ROW + ((lane >> 4) * 16);
    uint32_t bBase = smb + (SPLITA ? 2 * PL : PL);
#pragma unroll
    for (int bt = 0; bt < 2; bt++)
        bAddr[bt] = bBase + (wn * 32 + bt * 16 + ((lane >> 4) & 1) * 8 + (lane & 7)) * LDS_ROW
                  + (((lane >> 3) & 1) * 16);

    float acc[4][4][4];
#pragma unroll
    for (int i = 0; i < 4; i++)
#pragma unroll
        for (int j = 0; j < 4; j++)
#pragma unroll
            for (int k = 0; k < 4; k++) acc[i][j][k] = 0.0f;

    auto issue = [&](int ks, int stg) {
        uint32_t so = stg * STG_SZ;
#pragma unroll
        for (int c = 0; c < 2; c++) {
            if (SPLITA) {
                CP16(dst + so + c * 16,          srcA + ks * 64 + c * 16);          // A_hi
                CP16(dst + so + PL + c * 16,     srcA + 512 + ks * 64 + c * 16);    // A_lo
                CP16(dst + so + 2 * PL + c * 16, srcB + ks * 64 + c * 16);          // B
            } else {
                CP16(dst + so + c * 16,          srcA + ks * 64 + c * 16);          // A
                CP16(dst + so + PL + c * 16,     srcB + ks * 64 + c * 16);          // B_hi
                CP16(dst + so + 2 * PL + c * 16, srcB + 512 + ks * 64 + c * 16);    // B_lo
            }
        }
    };

    issue(0, 0); CP_COMMIT();
    issue(1, 1); CP_COMMIT();

    int stg = 0;
#pragma unroll 1
    for (int ks = 0; ks < 8; ks++) {
        CP_WAIT1();
        __syncthreads();
        if (ks < 6) { issue(ks + 2, (stg + 2) % 3); CP_COMMIT(); }
        uint32_t so = stg * STG_SZ;
#pragma unroll
        for (int kk = 0; kk < 2; kk++) {
            uint32_t ko = so + kk * 32;
            if (SPLITA) {
                uint32_t a_h[4][4], a_l[4][4], b[2][4];
#pragma unroll
                for (int mt = 0; mt < 4; mt++) {
                    LDSM_X4(a_h[mt], aAddr[mt] + ko);
                    LDSM_X4(a_l[mt], aAddr[mt] + ko + PL);
                }
#pragma unroll
                for (int bt = 0; bt < 2; bt++) LDSM_X4(b[bt], bAddr[bt] + ko);
#pragma unroll
                for (int mt = 0; mt < 4; mt++)
#pragma unroll
                    for (int nt = 0; nt < 4; nt++)
                        MMA16816(acc[mt][nt], a_h[mt], (&b[nt >> 1][(nt & 1) * 2]));
#pragma unroll
                for (int mt = 0; mt < 4; mt++)
#pragma unroll
                    for (int nt = 0; nt < 4; nt++)
                        MMA16816(acc[mt][nt], a_l[mt], (&b[nt >> 1][(nt & 1) * 2]));
            } else {
                uint32_t a[4][4], b_h[2][4], b_l[2][4];
#pragma unroll
                for (int mt = 0; mt < 4; mt++) LDSM_X4(a[mt], aAddr[mt] + ko);
#pragma unroll
                for (int bt = 0; bt < 2; bt++) {
                    LDSM_X4(b_h[bt], bAddr[bt] + ko);
                    LDSM_X4(b_l[bt], bAddr[bt] + ko + PL);
                }
#pragma unroll
                for (int mt = 0; mt < 4; mt++)
#pragma unroll
                    for (int nt = 0; nt < 4; nt++)
                        MMA16816(acc[mt][nt], a[mt], (&b_h[nt >> 1][(nt & 1) * 2]));
#pragma unroll
                for (int mt = 0; mt < 4; mt++)
#pragma unroll
                    for (int nt = 0; nt < 4; nt++)
                        MMA16816(acc[mt][nt], a[mt], (&b_l[nt >> 1][(nt & 1) * 2]));
            }
        }
        stg = (stg + 1) % 3;
    }

    // ---- epilogue ----
#pragma unroll
    for (int mt = 0; mt < 4; mt++) {
        int r0 = m0 + wm * 64 + mt * 16 + (lane >> 2);
        float rb0 = 0.f, rb1 = 0.f;
        if (ROWBIAS) { rb0 = bias[r0]; rb1 = bias[r0 + 8]; }
#pragma unroll
        for (int nt = 0; nt < 4; nt++) {
            int col = n0 + wn * 32 + nt * 8 + (lane & 3) * 2;
            float cb0 = 0.f, cb1 = 0.f;
            if (!ROWBIAS) { cb0 = bias[col]; cb1 = bias[col + 1]; }
            float* p = C + (size_t)r0 * ldc + col;
            float2 v;
            v.x = acc[mt][nt][0] + (ROWBIAS ? rb0 : cb0);
            v.y = acc[mt][nt][1] + (ROWBIAS ? rb0 : cb1);
            *(float2*)p = v;
            v.x = acc[mt][nt][2] + (ROWBIAS ? rb1 : cb0);
            v.y = acc[mt][nt][3] + (ROWBIAS ? rb1 : cb1);
            *(float2*)(p + (size_t)8 * ldc) = v;
        }
    }
}

// ---------------- attention: gather projected K/V rows, 9-tap softmax ----------------
__global__ __launch_bounds__(256)
void attn_kernel(const float* __restrict__ QKV, const int* __restrict__ idx,
                 __half* __restrict__ OUT2)
{
    int p0   = blockIdx.x << 5;
    int warp = threadIdx.x >> 5;
    int lane = threadIdx.x & 31;
    const float scale = 0.17677669529663687f;  // 1/sqrt(32)

#pragma unroll 1
    for (int task = warp; task < 256; task += 8) {
        int p  = task >> 3;
        int h  = task & 7;
        int pg = p0 + p;
        const int* ip = idx + pg * 9;
        int r[9];
#pragma unroll
        for (int t = 0; t < 9; t++) r[t] = ip[t];
        int cb = h * 32 + lane;
        float qd = QKV[(size_t)pg * 768 + cb];
        float kv[9], vv[9];
#pragma unroll
        for (int t = 0; t < 9; t++) kv[t] = QKV[(size_t)r[t] * 768 + 256 + cb];
#pragma unroll
        for (int t = 0; t < 9; t++) vv[t] = QKV[(size_t)r[t] * 768 + 512 + cb];
        float lg[9];
#pragma unroll
        for (int t = 0; t < 9; t++) {
            float prod = qd * kv[t];
#pragma unroll
            for (int off = 16; off > 0; off >>= 1)
                prod += __shfl_xor_sync(0xffffffffu, prod, off);
            lg[t] = prod * scale;
        }
        float mx = lg[0];
#pragma unroll
        for (int t = 1; t < 9; t++) mx = fmaxf(mx, lg[t]);
        float den = 0.0f, e[9];
#pragma unroll
        for (int t = 0; t < 9; t++) { e[t] = __expf(lg[t] - mx); den += e[t]; }
        float inv = 1.0f / den;
        float o = 0.0f;
#pragma unroll
        for (int t = 0; t < 9; t++) o += e[t] * vv[t];
        float val = o * inv;
        __half hi = __float2half_rn(val);
        size_t oi = (size_t)pg * 512 + cb;
        OUT2[oi]       = hi;
        OUT2[oi + 256] = __float2half_rn(val - __half2float(hi));
    }
}

// ---------------- launch ----------------
extern "C" void kernel_launch(void* const* d_in, const int* in_sizes, int n_in,
                              void* d_out, int out_size)
{
    const float* x   = (const float*)d_in[0];
    const float* grd = (const float*)d_in[1];
    const float* wq  = (const float*)d_in[2];
    const float* bq  = (const float*)d_in[3];
    const float* wk  = (const float*)d_in[4];
    const float* bk  = (const float*)d_in[5];
    const float* wv  = (const float*)d_in[6];
    const float* bv  = (const float*)d_in[7];
    const float* wo  = (const float*)d_in[8];
    const float* bo  = (const float*)d_in[9];
    float* y = (float*)d_out;

    __half *XT2, *W, *OUT2;
    float *QKV, *bqkv;
    int* idx;
    cudaGetSymbolAddress((void**)&XT2,  g_XT2);
    cudaGetSymbolAddress((void**)&idx,  g_idx);
    cudaGetSymbolAddress((void**)&W,    g_W);
    cudaGetSymbolAddress((void**)&QKV,  g_QKV);
    cudaGetSymbolAddress((void**)&bqkv, g_bqkv);
    cudaGetSymbolAddress((void**)&OUT2, g_OUT2);

    cudaFuncSetAttribute(hmma_gemm<false, true >, cudaFuncAttributeMaxDynamicSharedMemorySize, SMEM_SZ);
    cudaFuncSetAttribute(hmma_gemm<true,  false>, cudaFuncAttributeMaxDynamicSharedMemorySize, SMEM_SZ);

    // 1) gather indices
    idx_kernel<<<NSAMP / 256, 256>>>(grd, idx);

    // 2) x -> XT2 (hi|lo fp16); weights fp16 + bias concat
    transpose_conv<<<dim3(HW / 32, CC / 32), dim3(32, 8)>>>(x, XT2);
    prep_weights<<<(4 * CC * CC + 768 + 255) / 256, 256>>>(
        wq, wk, wv, wo, bq, bk, bv, W, bqkv);

    // 3) fused QKV projection (A = XT2 split, B = W single), K=256, 2-pass
    hmma_gemm<false, true><<<dim3(6, HW / 128), 256, SMEM_SZ>>>(
        XT2, W, bqkv, QKV, 768);

    // 4) attention with gathered projected rows -> OUT2 (hi|lo fp16)
    attn_kernel<<<HW / 32, 256>>>(QKV, idx, OUT2);

    // 5) y = wo * OUT^T + bo   (A = wo single, B = OUT2 split)
    hmma_gemm<true, false><<<dim3(HW / 128, CC / 128), 256, SMEM_SZ>>>(
        W + (size_t)768 * 256, OUT2, bo, y, HW);
}

// round 9
// speedup vs baseline: 1.3633x; 1.0114x over previous
#include <cuda_runtime.h>
#include <cuda_fp16.h>
#include <cstdint>

// ---------------- problem constants ----------------
#define HH 128
#define WW 256
#define HW (HH*WW)          // 32768
#define CC 256
#define NSAMP (HW*9)        // 294912

// ---------------- static device scratch ----------------
__device__ __half g_XT2[(size_t)HW*512];     // [pixel][512] = x_hi | x_lo  (fp16)
__device__ int    g_idx[NSAMP];
__device__ __half g_W[(size_t)1024*256];     // rows 0-767 qkv, 768-1023 wo (fp16)
__device__ float  g_bqkv[3*CC];
__device__ __half g_QKVh[(size_t)HW*3*CC];   // [pixel][768] = Q|K|V  fp16  48MB
__device__ __half g_OUT2[(size_t)HW*512];    // [pixel][512] = out_hi | out_lo

// ---------------- helpers ----------------
__device__ __forceinline__ uint32_t smem_u32(const void* p) {
    uint32_t a;
    asm("{ .reg .u64 t; cvta.to.shared.u64 t, %1; cvt.u32.u64 %0, t; }" : "=r"(a) : "l"(p));
    return a;
}
#define LDSM_X4(r, a) \
    asm volatile("ldmatrix.sync.aligned.m8n8.x4.shared.b16 {%0,%1,%2,%3}, [%4];" \
        : "=r"((r)[0]), "=r"((r)[1]), "=r"((r)[2]), "=r"((r)[3]) : "r"(a))

#define MMA16816(d, a, b) \
    asm volatile("mma.sync.aligned.m16n8k16.row.col.f32.f16.f16.f32 " \
        "{%0,%1,%2,%3}, {%4,%5,%6,%7}, {%8,%9}, {%0,%1,%2,%3};" \
        : "+f"((d)[0]), "+f"((d)[1]), "+f"((d)[2]), "+f"((d)[3]) \
        : "r"((a)[0]), "r"((a)[1]), "r"((a)[2]), "r"((a)[3]), "r"((b)[0]), "r"((b)[1]))

#define CP16(dst, src) \
    asm volatile("cp.async.cg.shared.global [%0], [%1], 16;" :: "r"(dst), "l"(src))
#define CP_COMMIT() asm volatile("cp.async.commit_group;")
#define CP_WAIT1()  asm volatile("cp.async.wait_group 1;")

// SMEM: 3 stages x 3 planes(128x80B)
#define LDS_ROW 80
#define PL      (128*LDS_ROW)        // 10240 per plane
#define STG_SZ  (3*PL)               // 30720 per stage
#define SMEM_SZ (3*STG_SZ)           // 92160

// ---------------- index computation ----------------
__global__ void idx_kernel(const float* __restrict__ grid, int* __restrict__ idx)
{
    int s = blockIdx.x * 256 + threadIdx.x;
    if (s >= NSAMP) return;
    int p  = s / 9;
    int t  = s - p * 9;
    int h  = p >> 8;
    int w  = p & 255;
    int kh = t / 3;
    int kw = t - kh * 3;
    const float* g = grid + ((size_t)(h * 3 + kh) * 768 + (w * 3 + kw)) * 2;
    float fx = rintf(((g[0] + 1.0f) * 0.5f) * 255.0f);
    float fy = rintf(((g[1] + 1.0f) * 0.5f) * 127.0f);
    int ix = (int)fminf(fmaxf(fx, 0.0f), 255.0f);
    int iy = (int)fminf(fmaxf(fy, 0.0f), 127.0f);
    idx[s] = iy * WW + ix;
}

// ---------------- transpose x[C][HW] -> XT2 [HW][512] = hi|lo fp16 ----------------
__global__ void transpose_conv(const float* __restrict__ in, __half* __restrict__ o2)
{
    __shared__ float tile[32][33];
    int c0 = blockIdx.x * 32;   // hw
    int r0 = blockIdx.y * 32;   // channel
    int tx = threadIdx.x, ty = threadIdx.y;
#pragma unroll
    for (int i = 0; i < 32; i += 8)
        tile[ty + i][tx] = in[(size_t)(r0 + ty + i) * HW + c0 + tx];
    __syncthreads();
#pragma unroll
    for (int i = 0; i < 32; i += 8) {
        float v = tile[tx][ty + i];
        __half h = __float2half_rn(v);
        size_t o = (size_t)(c0 + ty + i) * 512 + r0 + tx;
        o2[o]       = h;
        o2[o + 256] = __float2half_rn(v - __half2float(h));
    }
}

// ---------------- fused weight/bias prep ----------------
__global__ void prep_weights(const float* __restrict__ wq, const float* __restrict__ wk,
                             const float* __restrict__ wv, const float* __restrict__ wo,
                             const float* __restrict__ bq, const float* __restrict__ bk,
                             const float* __restrict__ bv,
                             __half* __restrict__ W, float* __restrict__ bqkv)
{
    int i = blockIdx.x * 256 + threadIdx.x;
    if (i < 4 * CC * CC) {
        int m = i >> 16;
        int j = i & 0xFFFF;
        const float* src = (m == 0) ? wq : (m == 1) ? wk : (m == 2) ? wv : wo;
        W[i] = __float2half_rn(src[j]);
    } else {
        int j = i - 4 * CC * CC;
        if (j < 768)
            bqkv[j] = (j < 256) ? bq[j] : ((j < 512) ? bk[j - 256] : bv[j - 512]);
    }
}

// ---------------- HMMA fp16 2-pass GEMM, K=256, B-reuse, 3-stage cp.async ----------------
// SPLITA: A rows [512]=hi|lo, B rows [256]: acc += A_hi*B + A_lo*B
// else  : A rows [256],  B rows [512]=hi|lo: acc += A*B_hi + A*B_lo
// HALFOUT: C is fp16 [ldc], else fp32.  CTA 128x128, warp 64x32, 2 CTAs/SM.
template<bool ROWBIAS, bool SPLITA, bool HALFOUT>
__global__ __launch_bounds__(256, 2)
void hmma_gemm(const __half* __restrict__ A, const __half* __restrict__ B,
               const float* __restrict__ bias, void* __restrict__ Cv, int ldc)
{
    extern __shared__ __align__(16) char sm[];
    uint32_t smb = smem_u32(sm);
    int tid = threadIdx.x;
    int wid = tid >> 5, lane = tid & 31;
    int wm = wid >> 2, wn = wid & 3;
    int m0 = blockIdx.y * 128, n0 = blockIdx.x * 128;

    const int strideA = SPLITA ? 512 : 256;
    const int strideB = SPLITA ? 256 : 512;

    int row = tid >> 1, ch = (tid & 1) * 2;
    const char* srcA = (const char*)(A + (size_t)(m0 + row) * strideA) + ch * 16;
    const char* srcB = (const char*)(B + (size_t)(n0 + row) * strideB) + ch * 16;
    uint32_t dst = smb + row * LDS_ROW + ch * 16;

    uint32_t aAddr[4], bAddr[2];
#pragma unroll
    for (int mt = 0; mt < 4; mt++)
        aAddr[mt] = smb + (wm * 64 + mt * 16 + (lane & 15)) * LDS_ROW + ((lane >> 4) * 16);
    uint32_t bBase = smb + (SPLITA ? 2 * PL : PL);
#pragma unroll
    for (int bt = 0; bt < 2; bt++)
        bAddr[bt] = bBase + (wn * 32 + bt * 16 + ((lane >> 4) & 1) * 8 + (lane & 7)) * LDS_ROW
                  + (((lane >> 3) & 1) * 16);

    float acc[4][4][4];
#pragma unroll
    for (int i = 0; i < 4; i++)
#pragma unroll
        for (int j = 0; j < 4; j++)
#pragma unroll
            for (int k = 0; k < 4; k++) acc[i][j][k] = 0.0f;

    auto issue = [&](int ks, int stg) {
        uint32_t so = stg * STG_SZ;
#pragma unroll
        for (int c = 0; c < 2; c++) {
            if (SPLITA) {
                CP16(dst + so + c * 16,          srcA + ks * 64 + c * 16);
                CP16(dst + so + PL + c * 16,     srcA + 512 + ks * 64 + c * 16);
                CP16(dst + so + 2 * PL + c * 16, srcB + ks * 64 + c * 16);
            } else {
                CP16(dst + so + c * 16,          srcA + ks * 64 + c * 16);
                CP16(dst + so + PL + c * 16,     srcB + ks * 64 + c * 16);
                CP16(dst + so + 2 * PL + c * 16, srcB + 512 + ks * 64 + c * 16);
            }
        }
    };

    issue(0, 0); CP_COMMIT();
    issue(1, 1); CP_COMMIT();

    int stg = 0;
#pragma unroll 1
    for (int ks = 0; ks < 8; ks++) {
        CP_WAIT1();
        __syncthreads();
        if (ks < 6) { issue(ks + 2, (stg + 2) % 3); CP_COMMIT(); }
        uint32_t so = stg * STG_SZ;
#pragma unroll
        for (int kk = 0; kk < 2; kk++) {
            uint32_t ko = so + kk * 32;
            if (SPLITA) {
                uint32_t a_h[4][4], a_l[4][4], b[2][4];
#pragma unroll
                for (int mt = 0; mt < 4; mt++) {
                    LDSM_X4(a_h[mt], aAddr[mt] + ko);
                    LDSM_X4(a_l[mt], aAddr[mt] + ko + PL);
                }
#pragma unroll
                for (int bt = 0; bt < 2; bt++) LDSM_X4(b[bt], bAddr[bt] + ko);
#pragma unroll
                for (int mt = 0; mt < 4; mt++)
#pragma unroll
                    for (int nt = 0; nt < 4; nt++)
                        MMA16816(acc[mt][nt], a_h[mt], (&b[nt >> 1][(nt & 1) * 2]));
#pragma unroll
                for (int mt = 0; mt < 4; mt++)
#pragma unroll
                    for (int nt = 0; nt < 4; nt++)
                        MMA16816(acc[mt][nt], a_l[mt], (&b[nt >> 1][(nt & 1) * 2]));
            } else {
                uint32_t a[4][4], b_h[2][4], b_l[2][4];
#pragma unroll
                for (int mt = 0; mt < 4; mt++) LDSM_X4(a[mt], aAddr[mt] + ko);
#pragma unroll
                for (int bt = 0; bt < 2; bt++) {
                    LDSM_X4(b_h[bt], bAddr[bt] + ko);
                    LDSM_X4(b_l[bt], bAddr[bt] + ko + PL);
                }
#pragma unroll
                for (int mt = 0; mt < 4; mt++)
#pragma unroll
                    for (int nt = 0; nt < 4; nt++)
                        MMA16816(acc[mt][nt], a[mt], (&b_h[nt >> 1][(nt & 1) * 2]));
#pragma unroll
                for (int mt = 0; mt < 4; mt++)
#pragma unroll
                    for (int nt = 0; nt < 4; nt++)
                        MMA16816(acc[mt][nt], a[mt], (&b_l[nt >> 1][(nt & 1) * 2]));
            }
        }
        stg = (stg + 1) % 3;
    }

    // ---- epilogue ----
#pragma unroll
    for (int mt = 0; mt < 4; mt++) {
        int r0 = m0 + wm * 64 + mt * 16 + (lane >> 2);
        float rb0 = 0.f, rb1 = 0.f;
        if (ROWBIAS) { rb0 = bias[r0]; rb1 = bias[r0 + 8]; }
#pragma unroll
        for (int nt = 0; nt < 4; nt++) {
            int col = n0 + wn * 32 + nt * 8 + (lane & 3) * 2;
            float cb0 = 0.f, cb1 = 0.f;
            if (!ROWBIAS) { cb0 = bias[col]; cb1 = bias[col + 1]; }
            float v00 = acc[mt][nt][0] + (ROWBIAS ? rb0 : cb0);
            float v01 = acc[mt][nt][1] + (ROWBIAS ? rb0 : cb1);
            float v10 = acc[mt][nt][2] + (ROWBIAS ? rb1 : cb0);
            float v11 = acc[mt][nt][3] + (ROWBIAS ? rb1 : cb1);
            if (HALFOUT) {
                __half* C = (__half*)Cv;
                *(__half2*)(C + (size_t)r0 * ldc + col)       = __floats2half2_rn(v00, v01);
                *(__half2*)(C + (size_t)(r0 + 8) * ldc + col) = __floats2half2_rn(v10, v11);
            } else {
                float* C = (float*)Cv;
                *(float2*)(C + (size_t)r0 * ldc + col)       = make_float2(v00, v01);
                *(float2*)(C + (size_t)(r0 + 8) * ldc + col) = make_float2(v10, v11);
            }
        }
    }
}

// ---------------- attention: gather projected fp16 K/V rows, 9-tap softmax ----------------
__global__ __launch_bounds__(256)
void attn_kernel(const __half* __restrict__ QKV, const int* __restrict__ idx,
                 __half* __restrict__ OUT2)
{
    int p0   = blockIdx.x << 5;
    int warp = threadIdx.x >> 5;
    int lane = threadIdx.x & 31;
    const float scale = 0.17677669529663687f;  // 1/sqrt(32)

#pragma unroll 1
    for (int task = warp; task < 256; task += 8) {
        int p  = task >> 3;
        int h  = task & 7;
        int pg = p0 + p;
        const int* ip = idx + pg * 9;
        int r[9];
#pragma unroll
        for (int t = 0; t < 9; t++) r[t] = ip[t];
        int cb = h * 32 + lane;
        float qd = __half2float(QKV[(size_t)pg * 768 + cb]);
        float kv[9], vv[9];
#pragma unroll
        for (int t = 0; t < 9; t++) kv[t] = __half2float(QKV[(size_t)r[t] * 768 + 256 + cb]);
#pragma unroll
        for (int t = 0; t < 9; t++) vv[t] = __half2float(QKV[(size_t)r[t] * 768 + 512 + cb]);
        float lg[9];
#pragma unroll
        for (int t = 0; t < 9; t++) {
            float prod = qd * kv[t];
#pragma unroll
            for (int off = 16; off > 0; off >>= 1)
                prod += __shfl_xor_sync(0xffffffffu, prod, off);
            lg[t] = prod * scale;
        }
        float mx = lg[0];
#pragma unroll
        for (int t = 1; t < 9; t++) mx = fmaxf(mx, lg[t]);
        float den = 0.0f, e[9];
#pragma unroll
        for (int t = 0; t < 9; t++) { e[t] = __expf(lg[t] - mx); den += e[t]; }
        float inv = 1.0f / den;
        float o = 0.0f;
#pragma unroll
        for (int t = 0; t < 9; t++) o += e[t] * vv[t];
        float val = o * inv;
        __half hi = __float2half_rn(val);
        size_t oi = (size_t)pg * 512 + cb;
        OUT2[oi]       = hi;
        OUT2[oi + 256] = __float2half_rn(val - __half2float(hi));
    }
}

// ---------------- launch ----------------
extern "C" void kernel_launch(void* const* d_in, const int* in_sizes, int n_in,
                              void* d_out, int out_size)
{
    const float* x   = (const float*)d_in[0];
    const float* grd = (const float*)d_in[1];
    const float* wq  = (const float*)d_in[2];
    const float* bq  = (const float*)d_in[3];
    const float* wk  = (const float*)d_in[4];
    const float* bk  = (const float*)d_in[5];
    const float* wv  = (const float*)d_in[6];
    const float* bv  = (const float*)d_in[7];
    const float* wo  = (const float*)d_in[8];
    const float* bo  = (const float*)d_in[9];
    float* y = (float*)d_out;

    __half *XT2, *W, *OUT2, *QKVh;
    float *bqkv;
    int* idx;
    cudaGetSymbolAddress((void**)&XT2,   g_XT2);
    cudaGetSymbolAddress((void**)&idx,   g_idx);
    cudaGetSymbolAddress((void**)&W,     g_W);
    cudaGetSymbolAddress((void**)&QKVh,  g_QKVh);
    cudaGetSymbolAddress((void**)&bqkv,  g_bqkv);
    cudaGetSymbolAddress((void**)&OUT2,  g_OUT2);

    cudaFuncSetAttribute(hmma_gemm<false, true,  true >, cudaFuncAttributeMaxDynamicSharedMemorySize, SMEM_SZ);
    cudaFuncSetAttribute(hmma_gemm<true,  false, false>, cudaFuncAttributeMaxDynamicSharedMemorySize, SMEM_SZ);

    // 1) gather indices
    idx_kernel<<<NSAMP / 256, 256>>>(grd, idx);

    // 2) x -> XT2 (hi|lo fp16); weights fp16 + bias concat
    transpose_conv<<<dim3(HW / 32, CC / 32), dim3(32, 8)>>>(x, XT2);
    prep_weights<<<(4 * CC * CC + 768 + 255) / 256, 256>>>(
        wq, wk, wv, wo, bq, bk, bv, W, bqkv);

    // 3) fused QKV projection (A = XT2 split, B = W), K=256, 2-pass, fp16 out
    hmma_gemm<false, true, true><<<dim3(6, HW / 128), 256, SMEM_SZ>>>(
        XT2, W, bqkv, QKVh, 768);

    // 4) attention with gathered projected fp16 rows -> OUT2 (hi|lo fp16)
    attn_kernel<<<HW / 32, 256>>>(QKVh, idx, OUT2);

    // 5) y = wo * OUT^T + bo   (A = wo, B = OUT2 split), fp32 out
    hmma_gemm<true, false, false><<<dim3(HW / 128, CC / 128), 256, SMEM_SZ>>>(
        W + (size_t)768 * 256, OUT2, bo, y, HW);
}

// round 11
// speedup vs baseline: 1.6422x; 1.2045x over previous
#include <cuda_runtime.h>
#include <cuda_fp16.h>
#include <cstdint>

// ---------------- problem constants ----------------
#define HH 128
#define WW 256
#define HW (HH*WW)          // 32768
#define CC 256
#define NSAMP (HW*9)        // 294912

// ---------------- static device scratch ----------------
__device__ __half g_XT[(size_t)HW*256];      // [pixel][256] fp16
__device__ int    g_idx[NSAMP];
__device__ __half g_W[(size_t)1024*256];     // rows 0-767 qkv, 768-1023 wo (fp16)
__device__ float  g_bqkv[3*CC];
__device__ __half g_QKVh[(size_t)HW*3*CC];   // [pixel][768] = Q|K|V  fp16
__device__ __half g_OUT[(size_t)HW*256];     // [pixel][256] fp16

// ---------------- helpers ----------------
__device__ __forceinline__ uint32_t smem_u32(const void* p) {
    uint32_t a;
    asm("{ .reg .u64 t; cvta.to.shared.u64 t, %1; cvt.u32.u64 %0, t; }" : "=r"(a) : "l"(p));
    return a;
}
#define LDSM_X4(r, a) \
    asm volatile("ldmatrix.sync.aligned.m8n8.x4.shared.b16 {%0,%1,%2,%3}, [%4];" \
        : "=r"((r)[0]), "=r"((r)[1]), "=r"((r)[2]), "=r"((r)[3]) : "r"(a))

#define MMA16816(d, a, b) \
    asm volatile("mma.sync.aligned.m16n8k16.row.col.f32.f16.f16.f32 " \
        "{%0,%1,%2,%3}, {%4,%5,%6,%7}, {%8,%9}, {%0,%1,%2,%3};" \
        : "+f"((d)[0]), "+f"((d)[1]), "+f"((d)[2]), "+f"((d)[3]) \
        : "r"((a)[0]), "r"((a)[1]), "r"((a)[2]), "r"((a)[3]), "r"((b)[0]), "r"((b)[1]))

#define CP16(dst, src) \
    asm volatile("cp.async.cg.shared.global [%0], [%1], 16;" :: "r"(dst), "l"(src))
#define CP_COMMIT() asm volatile("cp.async.commit_group;")
#define CP_WAIT1()  asm volatile("cp.async.wait_group 1;")
#define CP_WAIT0()  asm volatile("cp.async.wait_group 0;")

// SMEM: 3 stages x 2 planes(128x80B)
#define LDS_ROW 80
#define PL      (128*LDS_ROW)        // 10240 per plane
#define STG_SZ  (2*PL)               // 20480 per stage
#define SMEM_SZ (3*STG_SZ)           // 61440

// ---------------- index computation ----------------
__global__ void idx_kernel(const float* __restrict__ grid, int* __restrict__ idx)
{
    int s = blockIdx.x * 256 + threadIdx.x;
    if (s >= NSAMP) return;
    int p  = s / 9;
    int t  = s - p * 9;
    int h  = p >> 8;
    int w  = p & 255;
    int kh = t / 3;
    int kw = t - kh * 3;
    const float* g = grid + ((size_t)(h * 3 + kh) * 768 + (w * 3 + kw)) * 2;
    float fx = rintf(((g[0] + 1.0f) * 0.5f) * 255.0f);
    float fy = rintf(((g[1] + 1.0f) * 0.5f) * 127.0f);
    int ix = (int)fminf(fmaxf(fx, 0.0f), 255.0f);
    int iy = (int)fminf(fmaxf(fy, 0.0f), 127.0f);
    idx[s] = iy * WW + ix;
}

// ---------------- transpose x[C][HW] -> XT [HW][C] fp16 ----------------
__global__ void transpose_conv(const float* __restrict__ in, __half* __restrict__ o)
{
    __shared__ float tile[32][33];
    int c0 = blockIdx.x * 32;   // hw
    int r0 = blockIdx.y * 32;   // channel
    int tx = threadIdx.x, ty = threadIdx.y;
#pragma unroll
    for (int i = 0; i < 32; i += 8)
        tile[ty + i][tx] = in[(size_t)(r0 + ty + i) * HW + c0 + tx];
    __syncthreads();
#pragma unroll
    for (int i = 0; i < 32; i += 8)
        o[(size_t)(c0 + ty + i) * 256 + r0 + tx] = __float2half_rn(tile[tx][ty + i]);
}

// ---------------- fused weight/bias prep ----------------
__global__ void prep_weights(const float* __restrict__ wq, const float* __restrict__ wk,
                             const float* __restrict__ wv, const float* __restrict__ wo,
                             const float* __restrict__ bq, const float* __restrict__ bk,
                             const float* __restrict__ bv,
                             __half* __restrict__ W, float* __restrict__ bqkv)
{
    int i = blockIdx.x * 256 + threadIdx.x;
    if (i < 4 * CC * CC) {
        int m = i >> 16;
        int j = i & 0xFFFF;
        const float* src = (m == 0) ? wq : (m == 1) ? wk : (m == 2) ? wv : wo;
        W[i] = __float2half_rn(src[j]);
    } else {
        int j = i - 4 * CC * CC;
        if (j < 768)
            bqkv[j] = (j < 256) ? bq[j] : ((j < 512) ? bk[j - 256] : bv[j - 512]);
    }
}

// ---------------- HMMA fp16 single-pass GEMM, K=256, 3-stage cp.async ----------------
// C[M][N] = A[M][256] * B[N][256]^T + bias.  CTA 128x128, warp 64x32.
// HALFOUT: C fp16, else fp32.  ROWBIAS: bias per m, else per n.
template<bool ROWBIAS, bool HALFOUT>
__global__ __launch_bounds__(256, 2)
void hmma_gemm(const __half* __restrict__ A, const __half* __restrict__ B,
               const float* __restrict__ bias, void* __restrict__ Cv, int ldc)
{
    extern __shared__ __align__(16) char sm[];
    uint32_t smb = smem_u32(sm);
    int tid = threadIdx.x;
    int wid = tid >> 5, lane = tid & 31;
    int wm = wid >> 2, wn = wid & 3;
    int m0 = blockIdx.y * 128, n0 = blockIdx.x * 128;

    int row = tid >> 1, ch = (tid & 1) * 2;
    const char* srcA = (const char*)(A + (size_t)(m0 + row) * 256) + ch * 16;
    const char* srcB = (const char*)(B + (size_t)(n0 + row) * 256) + ch * 16;
    uint32_t dst = smb + row * LDS_ROW + ch * 16;

    uint32_t aAddr[4], bAddr[2];
#pragma unroll
    for (int mt = 0; mt < 4; mt++)
        aAddr[mt] = smb + (wm * 64 + mt * 16 + (lane & 15)) * LDS_ROW + ((lane >> 4) * 16);
#pragma unroll
    for (int bt = 0; bt < 2; bt++)
        bAddr[bt] = smb + PL + (wn * 32 + bt * 16 + ((lane >> 4) & 1) * 8 + (lane & 7)) * LDS_ROW
                  + (((lane >> 3) & 1) * 16);

    float acc[4][4][4];
#pragma unroll
    for (int i = 0; i < 4; i++)
#pragma unroll
        for (int j = 0; j < 4; j++)
#pragma unroll
            for (int k = 0; k < 4; k++) acc[i][j][k] = 0.0f;

    auto issue = [&](int ks, int stg) {
        uint32_t so = stg * STG_SZ;
#pragma unroll
        for (int c = 0; c < 2; c++) {
            CP16(dst + so + c * 16,      srcA + ks * 64 + c * 16);
            CP16(dst + so + PL + c * 16, srcB + ks * 64 + c * 16);
        }
    };

    issue(0, 0); CP_COMMIT();
    issue(1, 1); CP_COMMIT();

    int stg = 0;
#pragma unroll 1
    for (int ks = 0; ks < 8; ks++) {
        // RACE FIX: at the final iteration only ONE group is pending — the one
        // that wrote the stage we are about to read — so wait_group 1 would let
        // us read it before completion. Drain fully on the last iteration.
        if (ks == 7) { CP_WAIT0(); } else { CP_WAIT1(); }
        __syncthreads();
        if (ks < 6) { issue(ks + 2, (stg + 2) % 3); CP_COMMIT(); }
        uint32_t so = stg * STG_SZ;
#pragma unroll
        for (int kk = 0; kk < 2; kk++) {
            uint32_t ko = so + kk * 32;
            uint32_t a[4][4], b[2][4];
#pragma unroll
            for (int mt = 0; mt < 4; mt++) LDSM_X4(a[mt], aAddr[mt] + ko);
#pragma unroll
            for (int bt = 0; bt < 2; bt++) LDSM_X4(b[bt], bAddr[bt] + ko);
#pragma unroll
            for (int mt = 0; mt < 4; mt++)
#pragma unroll
                for (int nt = 0; nt < 4; nt++)
                    MMA16816(acc[mt][nt], a[mt], (&b[nt >> 1][(nt & 1) * 2]));
        }
        stg = (stg + 1) % 3;
    }

    // ---- epilogue ----
#pragma unroll
    for (int mt = 0; mt < 4; mt++) {
        int r0 = m0 + wm * 64 + mt * 16 + (lane >> 2);
        float rb0 = 0.f, rb1 = 0.f;
        if (ROWBIAS) { rb0 = bias[r0]; rb1 = bias[r0 + 8]; }
#pragma unroll
        for (int nt = 0; nt < 4; nt++) {
            int col = n0 + wn * 32 + nt * 8 + (lane & 3) * 2;
            float cb0 = 0.f, cb1 = 0.f;
            if (!ROWBIAS) { cb0 = bias[col]; cb1 = bias[col + 1]; }
            float v00 = acc[mt][nt][0] + (ROWBIAS ? rb0 : cb0);
            float v01 = acc[mt][nt][1] + (ROWBIAS ? rb0 : cb1);
            float v10 = acc[mt][nt][2] + (ROWBIAS ? rb1 : cb0);
            float v11 = acc[mt][nt][3] + (ROWBIAS ? rb1 : cb1);
            if (HALFOUT) {
                __half* C = (__half*)Cv;
                *(__half2*)(C + (size_t)r0 * ldc + col)       = __floats2half2_rn(v00, v01);
                *(__half2*)(C + (size_t)(r0 + 8) * ldc + col) = __floats2half2_rn(v10, v11);
            } else {
                float* C = (float*)Cv;
                *(float2*)(C + (size_t)r0 * ldc + col)       = make_float2(v00, v01);
                *(float2*)(C + (size_t)(r0 + 8) * ldc + col) = make_float2(v10, v11);
            }
        }
    }
}

// ---------------- attention: gather projected fp16 K/V rows, 9-tap softmax ----------------
__global__ __launch_bounds__(256)
void attn_kernel(const __half* __restrict__ QKV, const int* __restrict__ idx,
                 __half* __restrict__ OUT)
{
    int p0   = blockIdx.x << 5;
    int warp = threadIdx.x >> 5;
    int lane = threadIdx.x & 31;
    const float scale = 0.17677669529663687f;  // 1/sqrt(32)

#pragma unroll 1
    for (int task = warp; task < 256; task += 8) {
        int p  = task >> 3;
        int h  = task & 7;
        int pg = p0 + p;
        const int* ip = idx + pg * 9;
        int r[9];
#pragma unroll
        for (int t = 0; t < 9; t++) r[t] = ip[t];
        int cb = h * 32 + lane;
        float qd = __half2float(QKV[(size_t)pg * 768 + cb]);
        float kv[9], vv[9];
#pragma unroll
        for (int t = 0; t < 9; t++) kv[t] = __half2float(QKV[(size_t)r[t] * 768 + 256 + cb]);
#pragma unroll
        for (int t = 0; t < 9; t++) vv[t] = __half2float(QKV[(size_t)r[t] * 768 + 512 + cb]);
        float lg[9];
#pragma unroll
        for (int t = 0; t < 9; t++) {
            float prod = qd * kv[t];
#pragma unroll
            for (int off = 16; off > 0; off >>= 1)
                prod += __shfl_xor_sync(0xffffffffu, prod, off);
            lg[t] = prod * scale;
        }
        float mx = lg[0];
#pragma unroll
        for (int t = 1; t < 9; t++) mx = fmaxf(mx, lg[t]);
        float den = 0.0f, e[9];
#pragma unroll
        for (int t = 0; t < 9; t++) { e[t] = __expf(lg[t] - mx); den += e[t]; }
        float inv = 1.0f / den;
        float o = 0.0f;
#pragma unroll
        for (int t = 0; t < 9; t++) o += e[t] * vv[t];
        OUT[(size_t)pg * 256 + cb] = __float2half_rn(o * inv);
    }
}

// ---------------- launch ----------------
extern "C" void kernel_launch(void* const* d_in, const int* in_sizes, int n_in,
                              void* d_out, int out_size)
{
    const float* x   = (const float*)d_in[0];
    const float* grd = (const float*)d_in[1];
    const float* wq  = (const float*)d_in[2];
    const float* bq  = (const float*)d_in[3];
    const float* wk  = (const float*)d_in[4];
    const float* bk  = (const float*)d_in[5];
    const float* wv  = (const float*)d_in[6];
    const float* bv  = (const float*)d_in[7];
    const float* wo  = (const float*)d_in[8];
    const float* bo  = (const float*)d_in[9];
    float* y = (float*)d_out;

    __half *XT, *W, *OUT, *QKVh;
    float *bqkv;
    int* idx;
    cudaGetSymbolAddress((void**)&XT,    g_XT);
    cudaGetSymbolAddress((void**)&idx,   g_idx);
    cudaGetSymbolAddress((void**)&W,     g_W);
    cudaGetSymbolAddress((void**)&QKVh,  g_QKVh);
    cudaGetSymbolAddress((void**)&bqkv,  g_bqkv);
    cudaGetSymbolAddress((void**)&OUT,   g_OUT);

    cudaFuncSetAttribute(hmma_gemm<false, true >, cudaFuncAttributeMaxDynamicSharedMemorySize, SMEM_SZ);
    cudaFuncSetAttribute(hmma_gemm<true,  false>, cudaFuncAttributeMaxDynamicSharedMemorySize, SMEM_SZ);

    // 1) gather indices
    idx_kernel<<<NSAMP / 256, 256>>>(grd, idx);

    // 2) x -> XT fp16; weights fp16 + bias concat
    transpose_conv<<<dim3(HW / 32, CC / 32), dim3(32, 8)>>>(x, XT);
    prep_weights<<<(4 * CC * CC + 768 + 255) / 256, 256>>>(
        wq, wk, wv, wo, bq, bk, bv, W, bqkv);

    // 3) fused QKV projection (single-pass fp16), fp16 out
    hmma_gemm<false, true><<<dim3(6, HW / 128), 256, SMEM_SZ>>>(
        XT, W, bqkv, QKVh, 768);

    // 4) attention with gathered projected fp16 rows -> OUT fp16
    attn_kernel<<<HW / 32, 256>>>(QKVh, idx, OUT);

    // 5) y = wo * OUT^T + bo   (single-pass fp16), fp32 out
    hmma_gemm<true, false><<<dim3(HW / 128, CC / 128), 256, SMEM_SZ>>>(
        W + (size_t)768 * 256, OUT, bo, y, HW);
}